// round 12
// baseline (speedup 1.0000x reference)
#include <cuda_runtime.h>

#define NN 100000
#define NE 1600000
#define NF 128
#define NG 256

// ---- scratch (static device globals; 16B-aligned for vector access) ----
__device__ int   g_is64;                             // 1 if indices are int64
__device__ int   g_degi[NN];                         // in-degree histogram
__device__ int   g_off[NN + 1];                      // CSR offsets
__device__ int   g_cur[NN];                          // binning cursors
__device__ int   g_srcbin[NE];                       // src node id per CSR slot
__device__ __align__(16) float g_agg[(size_t)NN * NF];
__device__ __align__(16) float g_h1[(size_t)NN * NF];
__device__ __align__(16) float g_h2[(size_t)NN * NF];

// Uniform-branch index load for int32 or int64 buffers.
// Clamped to [0, NN): if dtype detection were ever wrong this yields a finite
// rel_err (diagnosable) instead of an OOB trap.
__device__ __forceinline__ int load_idx(const void* p, long long i) {
    int v;
    if (g_is64) v = (int)((const long long*)p)[i];
    else        v = ((const int*)p)[i];
    return min(max(v, 0), NN - 1);
}

// Detect index dtype from edge_index (values random in [0, NN)):
// int64 little-endian => every odd int32 word (high half) is 0.
// For int32 data, P(16 random odd words all zero) ~ (1e-5)^16 ~ 0.
__global__ void detect_kernel(const int* __restrict__ ei32) {
    if (threadIdx.x == 0 && blockIdx.x == 0) {
        int z = 1;
        #pragma unroll
        for (int i = 1; i < 32; i += 2) z &= (ei32[i] == 0);
        g_is64 = z;
    }
}

__global__ void zero_deg_kernel() {
    int i = blockIdx.x * blockDim.x + threadIdx.x;
    if (i < NN) g_degi[i] = 0;
}

__global__ void hist_kernel(const void* __restrict__ ei) {
    int e = blockIdx.x * blockDim.x + threadIdx.x;
    if (e < NE) {
        int d = load_idx(ei, (long long)NE + e);
        atomicAdd(&g_degi[d], 1);
    }
}

// Single-block exclusive scan of g_degi -> g_off (and init g_cur).
__global__ __launch_bounds__(1024) void scan_kernel() {
    __shared__ int part[1024];
    int t = threadIdx.x;
    const int CH = (NN + 1023) / 1024;   // 98
    int start = t * CH;
    int end = min(start + CH, NN);
    int s = 0;
    for (int i = start; i < end; ++i) s += g_degi[i];
    part[t] = s;
    __syncthreads();
    for (int off = 1; off < 1024; off <<= 1) {
        int v = (t >= off) ? part[t - off] : 0;
        __syncthreads();
        part[t] += v;
        __syncthreads();
    }
    int running = part[t] - s;   // exclusive base for this chunk
    for (int i = start; i < end; ++i) {
        g_off[i] = running;
        g_cur[i] = running;
        running += g_degi[i];
    }
    if (t == 1023) g_off[NN] = part[1023];
}

__global__ void bin_kernel(const void* __restrict__ ei) {
    int e = blockIdx.x * blockDim.x + threadIdx.x;
    if (e >= NE) return;
    int d = load_idx(ei, (long long)NE + e);
    int pos = atomicAdd(&g_cur[d], 1);
    g_srcbin[pos] = load_idx(ei, e);
}

// Gather-mean aggregation: one warp per node. LAYER resolved at compile time.
template <int LAYER>
__global__ void gather_agg_kernel(const float* __restrict__ x) {
    int w = blockIdx.x * (blockDim.x >> 5) + (threadIdx.x >> 5);
    int lane = threadIdx.x & 31;
    if (w >= NN) return;

    int beg = g_off[w];
    int end = g_off[w + 1];
    float4 acc = make_float4(0.f, 0.f, 0.f, 0.f);

    for (int j0 = beg; j0 < end; j0 += 32) {
        int m = min(32, end - j0);
        int mysrc = (lane < m) ? g_srcbin[j0 + lane] : 0;   // coalesced index load
        #pragma unroll 4
        for (int i = 0; i < m; ++i) {
            int s = __shfl_sync(0xffffffffu, mysrc, i);
            float4 v;
            if (LAYER == 0) v = *((const float4*)(x + (size_t)s * NF) + lane);
            else            v = *((const float4*)(g_h1 + (size_t)s * NF) + lane);
            acc.x += v.x; acc.y += v.y; acc.z += v.z; acc.w += v.w;
        }
    }
    float rd = 1.f / (float)max(end - beg, 1);
    acc.x *= rd; acc.y *= rd; acc.z *= rd; acc.w *= rd;
    *((float4*)(g_agg + (size_t)w * NF) + lane) = acc;
}

// Fused SAGE layer: C = relu( g_agg @ Wl + A @ Wr + bias ); g_agg already mean.
// LAYER 0: A = x param, C = g_h1.  LAYER 1: A = g_h1, C = g_h2.
// BM=128, BN=128, BK=16, 256 threads, 8x8 register blocking, fp32.
template <int LAYER>
__global__ __launch_bounds__(256) void sage_gemm(
    const float* __restrict__ x,
    const float* __restrict__ Wl, const float* __restrict__ Wr,
    const float* __restrict__ bias)
{
    __shared__ __align__(16) float As[16][128];   // k-major: conflict-free frag reads
    __shared__ __align__(16) float Bs[16][128];
    __shared__ float bias_s[128];

    int tid = threadIdx.x;
    int tx = tid & 15;   // col group  (cols tx*8 .. tx*8+7)
    int ty = tid >> 4;   // row group  (rows ty*8 .. ty*8+7)
    int row0 = blockIdx.x * 128;

    if (tid < 128) bias_s[tid] = bias[tid];
    __syncthreads();

    float acc[8][8];
    #pragma unroll
    for (int i = 0; i < 8; ++i)
        #pragma unroll
        for (int j = 0; j < 8; ++j) acc[i][j] = 0.f;

    #pragma unroll 1
    for (int phase = 0; phase < 2; ++phase) {
        const float* Wp = phase ? Wr : Wl;
        #pragma unroll 1
        for (int kt = 0; kt < 8; ++kt) {
            int k0 = kt * 16;
            // A tile: 128 rows x 16 k, transposed into As[k][row]
            #pragma unroll
            for (int i = 0; i < 2; ++i) {
                int u = tid + i * 256;
                int r = u >> 2;
                int c = (u & 3) << 2;
                int gr = row0 + r;
                float4 v = make_float4(0.f, 0.f, 0.f, 0.f);
                if (gr < NN) {
                    size_t idx = (size_t)gr * NF + k0 + c;
                    if (phase == 0) {
                        v = *(const float4*)(g_agg + idx);
                    } else {
                        if (LAYER == 0) v = *(const float4*)(x + idx);
                        else            v = *(const float4*)(g_h1 + idx);
                    }
                }
                As[c + 0][r] = v.x;
                As[c + 1][r] = v.y;
                As[c + 2][r] = v.z;
                As[c + 3][r] = v.w;
            }
            // B tile: 16 k-rows x 128 cols (row-major weights, coalesced)
            #pragma unroll
            for (int i = 0; i < 2; ++i) {
                int u = tid + i * 256;
                int kr = u >> 5;
                int c = (u & 31) << 2;
                *(float4*)&Bs[kr][c] = *(const float4*)(Wp + (size_t)(k0 + kr) * NF + c);
            }
            __syncthreads();
            #pragma unroll
            for (int kk = 0; kk < 16; ++kk) {
                float a[8], b[8];
                *(float4*)&a[0] = *(const float4*)&As[kk][ty * 8];
                *(float4*)&a[4] = *(const float4*)&As[kk][ty * 8 + 4];
                *(float4*)&b[0] = *(const float4*)&Bs[kk][tx * 8];
                *(float4*)&b[4] = *(const float4*)&Bs[kk][tx * 8 + 4];
                #pragma unroll
                for (int i = 0; i < 8; ++i)
                    #pragma unroll
                    for (int j = 0; j < 8; ++j)
                        acc[i][j] = fmaf(a[i], b[j], acc[i][j]);
            }
            __syncthreads();
        }
    }

    #pragma unroll
    for (int i = 0; i < 8; ++i) {
        int gr = row0 + ty * 8 + i;
        if (gr < NN) {
            #pragma unroll
            for (int j0 = 0; j0 < 8; j0 += 4) {
                int col = tx * 8 + j0;
                float4 v;
                v.x = fmaxf(acc[i][j0 + 0] + bias_s[col + 0], 0.f);
                v.y = fmaxf(acc[i][j0 + 1] + bias_s[col + 1], 0.f);
                v.z = fmaxf(acc[i][j0 + 2] + bias_s[col + 2], 0.f);
                v.w = fmaxf(acc[i][j0 + 3] + bias_s[col + 3], 0.f);
                if (LAYER == 0) *(float4*)(g_h1 + (size_t)gr * NF + col) = v;
                else            *(float4*)(g_h2 + (size_t)gr * NF + col) = v;
            }
        }
    }
}

// Readout: one block (128 threads) per graph; batch sorted -> contiguous range.
// out[g] = dot(mean_rows(h2[range]), Wfc) + bfc. Atomic-free, deterministic.
__global__ __launch_bounds__(128) void readout_kernel(
    const void* __restrict__ batch,
    const float* __restrict__ Wfc, const float* __restrict__ bfc,
    float* __restrict__ out)
{
    __shared__ int range_s[2];
    __shared__ float red[128];
    int g = blockIdx.x;
    int t = threadIdx.x;

    if (t < 2) {
        int key = g + t;
        int lo = 0, hi = NN;
        while (lo < hi) {
            int mid = (lo + hi) >> 1;
            int bv;
            if (g_is64) bv = (int)((const long long*)batch)[mid];
            else        bv = ((const int*)batch)[mid];
            if (bv < key) lo = mid + 1; else hi = mid;
        }
        range_s[t] = lo;
    }
    __syncthreads();
    int beg = range_s[0], end = range_s[1];

    float s = 0.f;
    for (int r = beg; r < end; ++r) s += g_h2[(size_t)r * NF + t];  // coalesced across t
    float cnt = fmaxf((float)(end - beg), 1.f);
    red[t] = (s / cnt) * Wfc[t];
    __syncthreads();
    #pragma unroll
    for (int off = 64; off > 0; off >>= 1) {
        if (t < off) red[t] += red[t + off];
        __syncthreads();
    }
    if (t == 0) out[g] = red[0] + bfc[0];
}

extern "C" void kernel_launch(void* const* d_in, const int* in_sizes, int n_in,
                              void* d_out, int out_size) {
    const float* x     = (const float*)d_in[0];
    const void*  ei    = d_in[1];                 // int32 or int64; detected on device
    const void*  batch = d_in[2];
    const float* W1l   = (const float*)d_in[3];
    const float* b1    = (const float*)d_in[4];
    const float* W1r   = (const float*)d_in[5];
    const float* W2l   = (const float*)d_in[6];
    const float* b2    = (const float*)d_in[7];
    const float* W2r   = (const float*)d_in[8];
    const float* Wfc   = (const float*)d_in[9];
    const float* bfc   = (const float*)d_in[10];
    float* out = (float*)d_out;

    // dtype detection + CSR build (reused by both layers)
    detect_kernel<<<1, 32>>>((const int*)ei);
    zero_deg_kernel<<<(NN + 255) / 256, 256>>>();
    hist_kernel<<<(NE + 255) / 256, 256>>>(ei);
    scan_kernel<<<1, 1024>>>();
    bin_kernel<<<(NE + 255) / 256, 256>>>(ei);

    // layer 1: gather-mean x -> g_agg; fused GEMM -> g_h1
    gather_agg_kernel<0><<<(NN + 7) / 8, 256>>>(x);
    sage_gemm<0><<<(NN + 127) / 128, 256>>>(x, W1l, W1r, b1);

    // layer 2: gather-mean g_h1 -> g_agg; fused GEMM -> g_h2
    gather_agg_kernel<1><<<(NN + 7) / 8, 256>>>(x);
    sage_gemm<1><<<(NN + 127) / 128, 256>>>(x, W2l, W2r, b2);

    // readout (atomic-free; batch sorted)
    readout_kernel<<<NG, 128>>>(batch, Wfc, bfc, out);
}

// round 13
// speedup vs baseline: 1.2730x; 1.2730x over previous
#include <cuda_runtime.h>

#define NN 100000
#define NE 1600000
#define NF 128
#define NG 256
#define NB 98              // ceil(NN / 1024)

// ---- scratch (static device globals; 16B-aligned for vector access) ----
__device__ int   g_is64;                             // 1 if indices are int64
__device__ int   g_degi[NN];                         // in-degree histogram
__device__ int   g_scan[NN];                         // block-local exclusive scan
__device__ int   g_part[NB];                         // per-block totals
__device__ int   g_partoff[NB];                      // scanned block bases
__device__ int   g_off[NN + 1];                      // CSR offsets
__device__ int   g_cur[NN];                          // binning cursors
__device__ int   g_srcbin[NE];                       // src node id per CSR slot
__device__ __align__(16) float g_agg[(size_t)NN * NF];
__device__ __align__(16) float g_h1[(size_t)NN * NF];
__device__ __align__(16) float g_h2[(size_t)NN * NF];

// Uniform-branch index load for int32 or int64 buffers, clamped to [0, NN).
__device__ __forceinline__ int load_idx(const void* p, long long i) {
    int v;
    if (g_is64) v = (int)((const long long*)p)[i];
    else        v = ((const int*)p)[i];
    return min(max(v, 0), NN - 1);
}

// Detect index dtype from edge_index (values random in [0, NN)):
// int64 little-endian => every odd int32 word (high half) is 0.
__global__ void detect_kernel(const int* __restrict__ ei32) {
    if (threadIdx.x == 0 && blockIdx.x == 0) {
        int z = 1;
        #pragma unroll
        for (int i = 1; i < 32; i += 2) z &= (ei32[i] == 0);
        g_is64 = z;
    }
}

__global__ void zero_deg_kernel() {
    int i = blockIdx.x * blockDim.x + threadIdx.x;
    if (i < NN) g_degi[i] = 0;
}

__global__ void hist_kernel(const void* __restrict__ ei) {
    int e = blockIdx.x * blockDim.x + threadIdx.x;
    if (e < NE) {
        int d = load_idx(ei, (long long)NE + e);
        atomicAdd(&g_degi[d], 1);
    }
}

// ---- 3-phase multi-block exclusive scan of g_degi -> g_off / g_cur ----
// Phase 1: block-local inclusive scan (smem Hillis-Steele); store local
// exclusive values and block totals. 98 blocks -> all SMs busy.
__global__ __launch_bounds__(1024) void scan_block_kernel() {
    __shared__ int sm[1024];
    int b = blockIdx.x, t = threadIdx.x;
    int i = b * 1024 + t;
    int v = (i < NN) ? g_degi[i] : 0;
    sm[t] = v;
    __syncthreads();
    for (int off = 1; off < 1024; off <<= 1) {
        int u = (t >= off) ? sm[t - off] : 0;
        __syncthreads();
        sm[t] += u;
        __syncthreads();
    }
    if (i < NN) g_scan[i] = sm[t] - v;       // exclusive within block
    if (t == 1023) g_part[b] = sm[t];        // block total
}

// Phase 2: single small block scans the 98 block totals.
__global__ __launch_bounds__(128) void scan_part_kernel() {
    __shared__ int sm[128];
    int t = threadIdx.x;
    int v = (t < NB) ? g_part[t] : 0;
    sm[t] = v;
    __syncthreads();
    for (int off = 1; off < 128; off <<= 1) {
        int u = (t >= off) ? sm[t - off] : 0;
        __syncthreads();
        sm[t] += u;
        __syncthreads();
    }
    if (t < NB) g_partoff[t] = sm[t] - v;    // exclusive base per block
    if (t == NB - 1) g_off[NN] = sm[t];      // grand total (= NE)
}

// Phase 3: add block bases; materialize g_off and g_cur.
__global__ __launch_bounds__(1024) void scan_add_kernel() {
    int i = blockIdx.x * 1024 + threadIdx.x;
    if (i < NN) {
        int o = g_scan[i] + g_partoff[blockIdx.x];
        g_off[i] = o;
        g_cur[i] = o;
    }
}

__global__ void bin_kernel(const void* __restrict__ ei) {
    int e = blockIdx.x * blockDim.x + threadIdx.x;
    if (e >= NE) return;
    int d = load_idx(ei, (long long)NE + e);
    int pos = atomicAdd(&g_cur[d], 1);
    g_srcbin[pos] = load_idx(ei, e);
}

// Gather-mean aggregation: one warp per node. LAYER resolved at compile time.
template <int LAYER>
__global__ void gather_agg_kernel(const float* __restrict__ x) {
    int w = blockIdx.x * (blockDim.x >> 5) + (threadIdx.x >> 5);
    int lane = threadIdx.x & 31;
    if (w >= NN) return;

    int beg = g_off[w];
    int end = g_off[w + 1];
    float4 acc = make_float4(0.f, 0.f, 0.f, 0.f);

    for (int j0 = beg; j0 < end; j0 += 32) {
        int m = min(32, end - j0);
        int mysrc = (lane < m) ? g_srcbin[j0 + lane] : 0;   // coalesced index load
        #pragma unroll 4
        for (int i = 0; i < m; ++i) {
            int s = __shfl_sync(0xffffffffu, mysrc, i);
            float4 v;
            if (LAYER == 0) v = *((const float4*)(x + (size_t)s * NF) + lane);
            else            v = *((const float4*)(g_h1 + (size_t)s * NF) + lane);
            acc.x += v.x; acc.y += v.y; acc.z += v.z; acc.w += v.w;
        }
    }
    float rd = 1.f / (float)max(end - beg, 1);
    acc.x *= rd; acc.y *= rd; acc.z *= rd; acc.w *= rd;
    *((float4*)(g_agg + (size_t)w * NF) + lane) = acc;
}

// Fused SAGE layer: C = relu( g_agg @ Wl + A @ Wr + bias ); g_agg already mean.
// LAYER 0: A = x param, C = g_h1.  LAYER 1: A = g_h1, C = g_h2.
// BM=128, BN=128, BK=16, 256 threads, 8x8 register blocking, fp32.
template <int LAYER>
__global__ __launch_bounds__(256) void sage_gemm(
    const float* __restrict__ x,
    const float* __restrict__ Wl, const float* __restrict__ Wr,
    const float* __restrict__ bias)
{
    __shared__ __align__(16) float As[16][128];   // k-major: conflict-free frag reads
    __shared__ __align__(16) float Bs[16][128];
    __shared__ float bias_s[128];

    int tid = threadIdx.x;
    int tx = tid & 15;   // col group  (cols tx*8 .. tx*8+7)
    int ty = tid >> 4;   // row group  (rows ty*8 .. ty*8+7)
    int row0 = blockIdx.x * 128;

    if (tid < 128) bias_s[tid] = bias[tid];
    __syncthreads();

    float acc[8][8];
    #pragma unroll
    for (int i = 0; i < 8; ++i)
        #pragma unroll
        for (int j = 0; j < 8; ++j) acc[i][j] = 0.f;

    #pragma unroll 1
    for (int phase = 0; phase < 2; ++phase) {
        const float* Wp = phase ? Wr : Wl;
        #pragma unroll 1
        for (int kt = 0; kt < 8; ++kt) {
            int k0 = kt * 16;
            // A tile: 128 rows x 16 k, transposed into As[k][row]
            #pragma unroll
            for (int i = 0; i < 2; ++i) {
                int u = tid + i * 256;
                int r = u >> 2;
                int c = (u & 3) << 2;
                int gr = row0 + r;
                float4 v = make_float4(0.f, 0.f, 0.f, 0.f);
                if (gr < NN) {
                    size_t idx = (size_t)gr * NF + k0 + c;
                    if (phase == 0) {
                        v = *(const float4*)(g_agg + idx);
                    } else {
                        if (LAYER == 0) v = *(const float4*)(x + idx);
                        else            v = *(const float4*)(g_h1 + idx);
                    }
                }
                As[c + 0][r] = v.x;
                As[c + 1][r] = v.y;
                As[c + 2][r] = v.z;
                As[c + 3][r] = v.w;
            }
            // B tile: 16 k-rows x 128 cols (row-major weights, coalesced)
            #pragma unroll
            for (int i = 0; i < 2; ++i) {
                int u = tid + i * 256;
                int kr = u >> 5;
                int c = (u & 31) << 2;
                *(float4*)&Bs[kr][c] = *(const float4*)(Wp + (size_t)(k0 + kr) * NF + c);
            }
            __syncthreads();
            #pragma unroll
            for (int kk = 0; kk < 16; ++kk) {
                float a[8], b[8];
                *(float4*)&a[0] = *(const float4*)&As[kk][ty * 8];
                *(float4*)&a[4] = *(const float4*)&As[kk][ty * 8 + 4];
                *(float4*)&b[0] = *(const float4*)&Bs[kk][tx * 8];
                *(float4*)&b[4] = *(const float4*)&Bs[kk][tx * 8 + 4];
                #pragma unroll
                for (int i = 0; i < 8; ++i)
                    #pragma unroll
                    for (int j = 0; j < 8; ++j)
                        acc[i][j] = fmaf(a[i], b[j], acc[i][j]);
            }
            __syncthreads();
        }
    }

    #pragma unroll
    for (int i = 0; i < 8; ++i) {
        int gr = row0 + ty * 8 + i;
        if (gr < NN) {
            #pragma unroll
            for (int j0 = 0; j0 < 8; j0 += 4) {
                int col = tx * 8 + j0;
                float4 v;
                v.x = fmaxf(acc[i][j0 + 0] + bias_s[col + 0], 0.f);
                v.y = fmaxf(acc[i][j0 + 1] + bias_s[col + 1], 0.f);
                v.z = fmaxf(acc[i][j0 + 2] + bias_s[col + 2], 0.f);
                v.w = fmaxf(acc[i][j0 + 3] + bias_s[col + 3], 0.f);
                if (LAYER == 0) *(float4*)(g_h1 + (size_t)gr * NF + col) = v;
                else            *(float4*)(g_h2 + (size_t)gr * NF + col) = v;
            }
        }
    }
}

// Readout: one block (128 threads) per graph; batch sorted -> contiguous range.
__global__ __launch_bounds__(128) void readout_kernel(
    const void* __restrict__ batch,
    const float* __restrict__ Wfc, const float* __restrict__ bfc,
    float* __restrict__ out)
{
    __shared__ int range_s[2];
    __shared__ float red[128];
    int g = blockIdx.x;
    int t = threadIdx.x;

    if (t < 2) {
        int key = g + t;
        int lo = 0, hi = NN;
        while (lo < hi) {
            int mid = (lo + hi) >> 1;
            int bv;
            if (g_is64) bv = (int)((const long long*)batch)[mid];
            else        bv = ((const int*)batch)[mid];
            if (bv < key) lo = mid + 1; else hi = mid;
        }
        range_s[t] = lo;
    }
    __syncthreads();
    int beg = range_s[0], end = range_s[1];

    float s = 0.f;
    for (int r = beg; r < end; ++r) s += g_h2[(size_t)r * NF + t];  // coalesced across t
    float cnt = fmaxf((float)(end - beg), 1.f);
    red[t] = (s / cnt) * Wfc[t];
    __syncthreads();
    #pragma unroll
    for (int off = 64; off > 0; off >>= 1) {
        if (t < off) red[t] += red[t + off];
        __syncthreads();
    }
    if (t == 0) out[g] = red[0] + bfc[0];
}

extern "C" void kernel_launch(void* const* d_in, const int* in_sizes, int n_in,
                              void* d_out, int out_size) {
    const float* x     = (const float*)d_in[0];
    const void*  ei    = d_in[1];                 // int32 or int64; detected on device
    const void*  batch = d_in[2];
    const float* W1l   = (const float*)d_in[3];
    const float* b1    = (const float*)d_in[4];
    const float* W1r   = (const float*)d_in[5];
    const float* W2l   = (const float*)d_in[6];
    const float* b2    = (const float*)d_in[7];
    const float* W2r   = (const float*)d_in[8];
    const float* Wfc   = (const float*)d_in[9];
    const float* bfc   = (const float*)d_in[10];
    float* out = (float*)d_out;

    // dtype detection + CSR build (reused by both layers)
    detect_kernel<<<1, 32>>>((const int*)ei);
    zero_deg_kernel<<<(NN + 255) / 256, 256>>>();
    hist_kernel<<<(NE + 255) / 256, 256>>>(ei);
    scan_block_kernel<<<NB, 1024>>>();
    scan_part_kernel<<<1, 128>>>();
    scan_add_kernel<<<NB, 1024>>>();
    bin_kernel<<<(NE + 255) / 256, 256>>>(ei);

    // layer 1: gather-mean x -> g_agg; fused GEMM -> g_h1
    gather_agg_kernel<0><<<(NN + 7) / 8, 256>>>(x);
    sage_gemm<0><<<(NN + 127) / 128, 256>>>(x, W1l, W1r, b1);

    // layer 2: gather-mean g_h1 -> g_agg; fused GEMM -> g_h2
    gather_agg_kernel<1><<<(NN + 7) / 8, 256>>>(x);
    sage_gemm<1><<<(NN + 127) / 128, 256>>>(x, W2l, W2r, b2);

    // readout (atomic-free; batch sorted)
    readout_kernel<<<NG, 128>>>(batch, Wfc, bfc, out);
}

// round 15
// speedup vs baseline: 1.3451x; 1.0567x over previous
#include <cuda_runtime.h>

#define NN 100000
#define NE 1600000
#define NF 128
#define NG 256
#define NB 98              // ceil(NN / 1024)

// ---- scratch (static device globals; 16B-aligned for vector access) ----
__device__ int   g_is64;                             // 1 if indices are int64
__device__ int   g_degi[NN];                         // in-degree histogram
__device__ int   g_scan[NN];                         // block-local exclusive scan
__device__ int   g_part[NB];                         // per-block totals
__device__ int   g_partoff[NB];                      // scanned block bases
__device__ int   g_off[NN + 1];                      // CSR offsets
__device__ int   g_cur[NN];                          // binning cursors
__device__ int   g_srcbin[NE];                       // src node id per CSR slot
__device__ __align__(16) float g_agg[(size_t)NN * NF];
__device__ __align__(16) float g_h1[(size_t)NN * NF];
__device__ __align__(16) float g_h2[(size_t)NN * NF];

// Uniform-branch index load for int32 or int64 buffers, clamped to [0, NN).
__device__ __forceinline__ int load_idx(const void* p, long long i) {
    int v;
    if (g_is64) v = (int)((const long long*)p)[i];
    else        v = ((const int*)p)[i];
    return min(max(v, 0), NN - 1);
}

// Detect index dtype from edge_index (values random in [0, NN)):
// int64 little-endian => every odd int32 word (high half) is 0.
__global__ void detect_kernel(const int* __restrict__ ei32) {
    if (threadIdx.x == 0 && blockIdx.x == 0) {
        int z = 1;
        #pragma unroll
        for (int i = 1; i < 32; i += 2) z &= (ei32[i] == 0);
        g_is64 = z;
    }
}

__global__ void zero_deg_kernel() {
    int i = blockIdx.x * blockDim.x + threadIdx.x;
    if (i < NN) g_degi[i] = 0;
}

__global__ void hist_kernel(const void* __restrict__ ei) {
    int e = blockIdx.x * blockDim.x + threadIdx.x;
    if (e < NE) {
        int d = load_idx(ei, (long long)NE + e);
        atomicAdd(&g_degi[d], 1);
    }
}

// ---- 3-phase multi-block exclusive scan of g_degi -> g_off / g_cur ----
__global__ __launch_bounds__(1024) void scan_block_kernel() {
    __shared__ int sm[1024];
    int b = blockIdx.x, t = threadIdx.x;
    int i = b * 1024 + t;
    int v = (i < NN) ? g_degi[i] : 0;
    sm[t] = v;
    __syncthreads();
    for (int off = 1; off < 1024; off <<= 1) {
        int u = (t >= off) ? sm[t - off] : 0;
        __syncthreads();
        sm[t] += u;
        __syncthreads();
    }
    if (i < NN) g_scan[i] = sm[t] - v;       // exclusive within block
    if (t == 1023) g_part[b] = sm[t];        // block total
}

__global__ __launch_bounds__(128) void scan_part_kernel() {
    __shared__ int sm[128];
    int t = threadIdx.x;
    int v = (t < NB) ? g_part[t] : 0;
    sm[t] = v;
    __syncthreads();
    for (int off = 1; off < 128; off <<= 1) {
        int u = (t >= off) ? sm[t - off] : 0;
        __syncthreads();
        sm[t] += u;
        __syncthreads();
    }
    if (t < NB) g_partoff[t] = sm[t] - v;    // exclusive base per block
    if (t == NB - 1) g_off[NN] = sm[t];      // grand total (= NE)
}

__global__ __launch_bounds__(1024) void scan_add_kernel() {
    int i = blockIdx.x * 1024 + threadIdx.x;
    if (i < NN) {
        int o = g_scan[i] + g_partoff[blockIdx.x];
        g_off[i] = o;
        g_cur[i] = o;
    }
}

__global__ void bin_kernel(const void* __restrict__ ei) {
    int e = blockIdx.x * blockDim.x + threadIdx.x;
    if (e >= NE) return;
    int d = load_idx(ei, (long long)NE + e);
    int pos = atomicAdd(&g_cur[d], 1);
    g_srcbin[pos] = load_idx(ei, e);
}

// Gather-mean aggregation: one warp per node. LAYER resolved at compile time.
template <int LAYER>
__global__ void gather_agg_kernel(const float* __restrict__ x) {
    int w = blockIdx.x * (blockDim.x >> 5) + (threadIdx.x >> 5);
    int lane = threadIdx.x & 31;
    if (w >= NN) return;

    int beg = g_off[w];
    int end = g_off[w + 1];
    float4 acc = make_float4(0.f, 0.f, 0.f, 0.f);

    for (int j0 = beg; j0 < end; j0 += 32) {
        int m = min(32, end - j0);
        int mysrc = (lane < m) ? g_srcbin[j0 + lane] : 0;   // coalesced index load
        #pragma unroll 4
        for (int i = 0; i < m; ++i) {
            int s = __shfl_sync(0xffffffffu, mysrc, i);
            float4 v;
            if (LAYER == 0) v = *((const float4*)(x + (size_t)s * NF) + lane);
            else            v = *((const float4*)(g_h1 + (size_t)s * NF) + lane);
            acc.x += v.x; acc.y += v.y; acc.z += v.z; acc.w += v.w;
        }
    }
    float rd = 1.f / (float)max(end - beg, 1);
    acc.x *= rd; acc.y *= rd; acc.z *= rd; acc.w *= rd;
    *((float4*)(g_agg + (size_t)w * NF) + lane) = acc;
}

// Fused SAGE layer: C = relu( g_agg @ Wl + A @ Wr + bias ); g_agg already mean.
// LAYER 0: A = x param, C = g_h1.  LAYER 1: A = g_h1, C = g_h2.
// BM=128, BN=128, BK=16, 256 threads, 8x8 register blocking.
// Inner product uses packed fp32 FFMA2 (fma.rn.f32x2): 2 fp32 FMAs/instr,
// IEEE fp32 exact — 2x fp32 pipe throughput on sm_103a.
template <int LAYER>
__global__ __launch_bounds__(256) void sage_gemm(
    const float* __restrict__ x,
    const float* __restrict__ Wl, const float* __restrict__ Wr,
    const float* __restrict__ bias)
{
    __shared__ __align__(16) float As[16][128];   // k-major: conflict-free frag reads
    __shared__ __align__(16) float Bs[16][128];
    __shared__ float bias_s[128];

    int tid = threadIdx.x;
    int tx = tid & 15;   // col group  (cols tx*8 .. tx*8+7)
    int ty = tid >> 4;   // row group  (rows ty*8 .. ty*8+7)
    int row0 = blockIdx.x * 128;

    if (tid < 128) bias_s[tid] = bias[tid];
    __syncthreads();

    // packed accumulators: acc2[i][j] = (C[row i][col 2j], C[row i][col 2j+1])
    unsigned long long acc2[8][4];
    #pragma unroll
    for (int i = 0; i < 8; ++i)
        #pragma unroll
        for (int j = 0; j < 4; ++j) acc2[i][j] = 0ull;   // (+0.f, +0.f)

    #pragma unroll 1
    for (int phase = 0; phase < 2; ++phase) {
        const float* Wp = phase ? Wr : Wl;
        #pragma unroll 1
        for (int kt = 0; kt < 8; ++kt) {
            int k0 = kt * 16;
            // A tile: 128 rows x 16 k, transposed into As[k][row]
            #pragma unroll
            for (int i = 0; i < 2; ++i) {
                int u = tid + i * 256;
                int r = u >> 2;
                int c = (u & 3) << 2;
                int gr = row0 + r;
                float4 v = make_float4(0.f, 0.f, 0.f, 0.f);
                if (gr < NN) {
                    size_t idx = (size_t)gr * NF + k0 + c;
                    if (phase == 0) {
                        v = *(const float4*)(g_agg + idx);
                    } else {
                        if (LAYER == 0) v = *(const float4*)(x + idx);
                        else            v = *(const float4*)(g_h1 + idx);
                    }
                }
                As[c + 0][r] = v.x;
                As[c + 1][r] = v.y;
                As[c + 2][r] = v.z;
                As[c + 3][r] = v.w;
            }
            // B tile: 16 k-rows x 128 cols (row-major weights, coalesced)
            #pragma unroll
            for (int i = 0; i < 2; ++i) {
                int u = tid + i * 256;
                int kr = u >> 5;
                int c = (u & 31) << 2;
                *(float4*)&Bs[kr][c] = *(const float4*)(Wp + (size_t)(k0 + kr) * NF + c);
            }
            __syncthreads();
            #pragma unroll
            for (int kk = 0; kk < 16; ++kk) {
                float a[8];
                *(float4*)&a[0] = *(const float4*)&As[kk][ty * 8];
                *(float4*)&a[4] = *(const float4*)&As[kk][ty * 8 + 4];
                // b fragment as 4 packed f32x2 pairs (32B-aligned in Bs)
                unsigned long long b2[4];
                {
                    ulonglong2 t0 = *(const ulonglong2*)&Bs[kk][tx * 8];
                    ulonglong2 t1 = *(const ulonglong2*)&Bs[kk][tx * 8 + 4];
                    b2[0] = t0.x; b2[1] = t0.y; b2[2] = t1.x; b2[3] = t1.y;
                }
                #pragma unroll
                for (int i = 0; i < 8; ++i) {
                    unsigned long long ad;
                    asm("mov.b64 %0, {%1, %1};" : "=l"(ad) : "f"(a[i]));
                    #pragma unroll
                    for (int j = 0; j < 4; ++j)
                        asm("fma.rn.f32x2 %0, %1, %2, %0;"
                            : "+l"(acc2[i][j]) : "l"(ad), "l"(b2[j]));
                }
            }
            __syncthreads();
        }
    }

    #pragma unroll
    for (int i = 0; i < 8; ++i) {
        int gr = row0 + ty * 8 + i;
        if (gr < NN) {
            float vals[8];
            #pragma unroll
            for (int j = 0; j < 4; ++j)
                asm("mov.b64 {%0, %1}, %2;"
                    : "=f"(vals[2 * j]), "=f"(vals[2 * j + 1]) : "l"(acc2[i][j]));
            #pragma unroll
            for (int j0 = 0; j0 < 8; j0 += 4) {
                int col = tx * 8 + j0;
                float4 v;
                v.x = fmaxf(vals[j0 + 0] + bias_s[col + 0], 0.f);
                v.y = fmaxf(vals[j0 + 1] + bias_s[col + 1], 0.f);
                v.z = fmaxf(vals[j0 + 2] + bias_s[col + 2], 0.f);
                v.w = fmaxf(vals[j0 + 3] + bias_s[col + 3], 0.f);
                if (LAYER == 0) *(float4*)(g_h1 + (size_t)gr * NF + col) = v;
                else            *(float4*)(g_h2 + (size_t)gr * NF + col) = v;
            }
        }
    }
}

// Readout: one block (128 threads) per graph; batch sorted -> contiguous range.
__global__ __launch_bounds__(128) void readout_kernel(
    const void* __restrict__ batch,
    const float* __restrict__ Wfc, const float* __restrict__ bfc,
    float* __restrict__ out)
{
    __shared__ int range_s[2];
    __shared__ float red[128];
    int g = blockIdx.x;
    int t = threadIdx.x;

    if (t < 2) {
        int key = g + t;
        int lo = 0, hi = NN;
        while (lo < hi) {
            int mid = (lo + hi) >> 1;
            int bv;
            if (g_is64) bv = (int)((const long long*)batch)[mid];
            else        bv = ((const int*)batch)[mid];
            if (bv < key) lo = mid + 1; else hi = mid;
        }
        range_s[t] = lo;
    }
    __syncthreads();
    int beg = range_s[0], end = range_s[1];

    float s = 0.f;
    for (int r = beg; r < end; ++r) s += g_h2[(size_t)r * NF + t];  // coalesced across t
    float cnt = fmaxf((float)(end - beg), 1.f);
    red[t] = (s / cnt) * Wfc[t];
    __syncthreads();
    #pragma unroll
    for (int off = 64; off > 0; off >>= 1) {
        if (t < off) red[t] += red[t + off];
        __syncthreads();
    }
    if (t == 0) out[g] = red[0] + bfc[0];
}

extern "C" void kernel_launch(void* const* d_in, const int* in_sizes, int n_in,
                              void* d_out, int out_size) {
    const float* x     = (const float*)d_in[0];
    const void*  ei    = d_in[1];                 // int32 or int64; detected on device
    const void*  batch = d_in[2];
    const float* W1l   = (const float*)d_in[3];
    const float* b1    = (const float*)d_in[4];
    const float* W1r   = (const float*)d_in[5];
    const float* W2l   = (const float*)d_in[6];
    const float* b2    = (const float*)d_in[7];
    const float* W2r   = (const float*)d_in[8];
    const float* Wfc   = (const float*)d_in[9];
    const float* bfc   = (const float*)d_in[10];
    float* out = (float*)d_out;

    // dtype detection + CSR build (reused by both layers)
    detect_kernel<<<1, 32>>>((const int*)ei);
    zero_deg_kernel<<<(NN + 255) / 256, 256>>>();
    hist_kernel<<<(NE + 255) / 256, 256>>>(ei);
    scan_block_kernel<<<NB, 1024>>>();
    scan_part_kernel<<<1, 128>>>();
    scan_add_kernel<<<NB, 1024>>>();
    bin_kernel<<<(NE + 255) / 256, 256>>>(ei);

    // layer 1: gather-mean x -> g_agg; fused GEMM -> g_h1
    gather_agg_kernel<0><<<(NN + 7) / 8, 256>>>(x);
    sage_gemm<0><<<(NN + 127) / 128, 256>>>(x, W1l, W1r, b1);

    // layer 2: gather-mean g_h1 -> g_agg; fused GEMM -> g_h2
    gather_agg_kernel<1><<<(NN + 7) / 8, 256>>>(x);
    sage_gemm<1><<<(NN + 127) / 128, 256>>>(x, W2l, W2r, b2);

    // readout (atomic-free; batch sorted)
    readout_kernel<<<NG, 128>>>(batch, Wfc, bfc, out);
}